// round 6
// baseline (speedup 1.0000x reference)
#include <cuda_runtime.h>
#include <cuda_fp16.h>
#include <cstdint>
#include <math.h>

#define NT 2048      // tokens
#define NH 1024      // hidden
#define NE 16        // experts
#define NK 4         // top-k
#define NG 4         // groups
#define NI 512       // moe intermediate
#define NISH 1024    // shared intermediate
#define RSCALE 2.5f
#define NA (NT*NK)
#define SK 40        // smem row stride in halves (32 + 8 pad)

// ---------------- scratch ----------------
static __device__ int   g_count[NE];
static __device__ int   g_off[NE+1];
static __device__ int   g_cur[NE];
static __device__ int   g_texp[NT*NK];
static __device__ float g_twt[NT*NK];
static __device__ int   g_tok[NA];
static __device__ float g_wslot[NA];
static __device__ int   g_slot[NT*NK];
static __device__ float g_y[(size_t)NA*NH];

// fp16 planes (pre-converted once per launch)
static __device__ half g_xh [(size_t)NT*NH];
static __device__ half g_hh [(size_t)NA*NI];        // routed h
static __device__ half g_shh[(size_t)NT*NISH];      // shared h
static __device__ half g_gwh [(size_t)NE*NI*NH],  g_gwls[(size_t)NE*NI*NH];
static __device__ half g_uwh [(size_t)NE*NI*NH],  g_uwls[(size_t)NE*NI*NH];
static __device__ half g_dwh [(size_t)NE*NH*NI],  g_dwls[(size_t)NE*NH*NI];
static __device__ half g_sgwh[(size_t)NISH*NH],   g_sgwls[(size_t)NISH*NH];
static __device__ half g_suwh[(size_t)NISH*NH],   g_suwls[(size_t)NISH*NH];
static __device__ half g_sdwh[(size_t)NH*NISH],   g_sdwls[(size_t)NH*NISH];

// ---------------- asm helpers ----------------
__device__ __forceinline__ uint32_t smem_u32(const void* p) {
    uint32_t a;
    asm("{ .reg .u64 t; cvta.to.shared.u64 t, %1; cvt.u32.u64 %0, t; }" : "=r"(a) : "l"(p));
    return a;
}
__device__ __forceinline__ void cpa16(uint32_t dst, const void* src, int sz) {
    asm volatile("cp.async.cg.shared.global [%0], [%1], 16, %2;"
        :: "r"(dst), "l"(src), "r"(sz) : "memory");
}
#define CP_COMMIT() asm volatile("cp.async.commit_group;" ::: "memory")
#define CP_WAIT1()  asm volatile("cp.async.wait_group 1;" ::: "memory")
#define CP_WAIT0()  asm volatile("cp.async.wait_group 0;" ::: "memory")

__device__ __forceinline__ void ldsm4(uint32_t& a0, uint32_t& a1, uint32_t& a2, uint32_t& a3,
                                      uint32_t addr) {
    asm volatile("ldmatrix.sync.aligned.m8n8.x4.shared.b16 {%0,%1,%2,%3}, [%4];"
        : "=r"(a0), "=r"(a1), "=r"(a2), "=r"(a3) : "r"(addr));
}
__device__ __forceinline__ void mma16816(float* c, const uint32_t* a, const uint32_t* b) {
    asm volatile("mma.sync.aligned.m16n8k16.row.col.f32.f16.f16.f32 "
        "{%0,%1,%2,%3}, {%4,%5,%6,%7}, {%8,%9}, {%0,%1,%2,%3};"
        : "+f"(c[0]), "+f"(c[1]), "+f"(c[2]), "+f"(c[3])
        : "r"(a[0]), "r"(a[1]), "r"(a[2]), "r"(a[3]), "r"(b[0]), "r"(b[1]));
}
__device__ __forceinline__ uint32_t hscale(uint32_t a) {   // * 2^-10 per half
    uint32_t r;
    asm("mul.f16x2 %0, %1, %2;" : "=r"(r) : "r"(a), "r"(0x14001400u));
    return r;
}

// ---------------- conversion kernels (16 elem/thread, MLP=4) ----------------
__global__ __launch_bounds__(256) void conv_pair_kernel(
        const float* __restrict__ src, half* __restrict__ hi,
        half* __restrict__ ls, int n) {
    const int i = (blockIdx.x*256 + threadIdx.x)*16;
    if (i >= n) return;
    float4 v[4];
    #pragma unroll
    for (int j = 0; j < 4; j++) v[j] = *(const float4*)(src + i + j*4);
    half ho[16], lo[16];
    #pragma unroll
    for (int j = 0; j < 4; j++) {
        const float* f = (const float*)&v[j];
        #pragma unroll
        for (int q = 0; q < 4; q++) {
            half h = __float2half(f[q]);
            ho[j*4+q] = h;
            lo[j*4+q] = __float2half((f[q] - __half2float(h))*1024.f);
        }
    }
    *(uint4*)(hi + i)     = *(uint4*)(ho);
    *(uint4*)(hi + i + 8) = *(uint4*)(ho + 8);
    *(uint4*)(ls + i)     = *(uint4*)(lo);
    *(uint4*)(ls + i + 8) = *(uint4*)(lo + 8);
}
__global__ __launch_bounds__(256) void conv_hi_kernel(
        const float* __restrict__ src, half* __restrict__ hi, int n) {
    const int i = (blockIdx.x*256 + threadIdx.x)*16;
    if (i >= n) return;
    float4 v[4];
    #pragma unroll
    for (int j = 0; j < 4; j++) v[j] = *(const float4*)(src + i + j*4);
    half ho[16];
    #pragma unroll
    for (int j = 0; j < 4; j++) {
        const float* f = (const float*)&v[j];
        #pragma unroll
        for (int q = 0; q < 4; q++) ho[j*4+q] = __float2half(f[q]);
    }
    *(uint4*)(hi + i)     = *(uint4*)(ho);
    *(uint4*)(hi + i + 8) = *(uint4*)(ho + 8);
}

// ---------------- routing ----------------
__global__ void zero_kernel() {
    if (threadIdx.x < NE) g_count[threadIdx.x] = 0;
}

__global__ void router_kernel(const float* __restrict__ x,
                              const float* __restrict__ wr,
                              const float* __restrict__ eb) {
    const int t = blockIdx.x;
    __shared__ float xs[NH];
    __shared__ float part[128];
    __shared__ float scores[NE];
    const int tid = threadIdx.x;
    for (int i = tid; i < NH; i += 128) xs[i] = x[(size_t)t*NH + i];
    __syncthreads();
    const int e = tid >> 3, p = tid & 7;
    float s = 0.f;
    const float* w = wr + (size_t)e*NH;
    for (int i = p; i < NH; i += 8) s += xs[i] * w[i];
    part[tid] = s;
    __syncthreads();
    if (tid < NE) {
        float v = 0.f;
        #pragma unroll
        for (int j = 0; j < 8; j++) v += part[tid*8 + j];
        scores[tid] = 1.f / (1.f + expf(-v));
    }
    __syncthreads();
    if (tid == 0) {
        float sc[NE];
        #pragma unroll
        for (int i = 0; i < NE; i++) sc[i] = scores[i] + eb[i];
        float gs[NG];
        #pragma unroll
        for (int g = 0; g < NG; g++) {
            float m1 = -1e30f, m2 = -1e30f;
            #pragma unroll
            for (int j = 0; j < 4; j++) {
                float v = sc[g*4 + j];
                if (v > m1) { m2 = m1; m1 = v; } else if (v > m2) m2 = v;
            }
            gs[g] = m1 + m2;
        }
        int g1 = 0;
        for (int g = 1; g < NG; g++) if (gs[g] > gs[g1]) g1 = g;
        int g2 = -1;
        for (int g = 0; g < NG; g++) {
            if (g == g1) continue;
            if (g2 < 0 || gs[g] > gs[g2]) g2 = g;
        }
        float msk[NE];
        #pragma unroll
        for (int i = 0; i < NE; i++) {
            int gi = i >> 2;
            msk[i] = (gi == g1 || gi == g2) ? sc[i] : 0.0f;
        }
        int idx[NK]; float tw[NK]; float sum = 0.f;
        #pragma unroll
        for (int k = 0; k < NK; k++) {
            int best = 0; float bv = -1e30f;
            for (int i = 0; i < NE; i++)
                if (msk[i] > bv) { bv = msk[i]; best = i; }
            msk[best] = -1e30f;
            idx[k] = best; tw[k] = scores[best]; sum += tw[k];
        }
        const float inv = RSCALE / (sum + 1e-20f);
        for (int k = 0; k < NK; k++) {
            g_texp[t*NK + k] = idx[k];
            g_twt[t*NK + k]  = tw[k] * inv;
            atomicAdd(&g_count[idx[k]], 1);
        }
    }
}

__global__ void prefix_kernel() {
    int o = 0;
    for (int e = 0; e < NE; e++) { g_off[e] = o; g_cur[e] = o; o += g_count[e]; }
    g_off[NE] = o;
}

__global__ void scatter_kernel() {
    int t = blockIdx.x*blockDim.x + threadIdx.x;
    if (t >= NT) return;
    for (int k = 0; k < NK; k++) {
        int e = g_texp[t*NK + k];
        int s = atomicAdd(&g_cur[e], 1);
        g_tok[s] = t;
        g_wslot[s] = g_twt[t*NK + k];
        g_slot[t*NK + k] = s;
    }
}

// ---------------- gate+up fused MMA (fp16, 2-product) ----------------
#define GU_BUFH (384*SK)
#define GU_SMEM (2*GU_BUFH*2 + 512)

__global__ __launch_bounds__(256, 2) void gateup_mma(
    const half* __restrict__ gwh, const half* __restrict__ gwls,
    const half* __restrict__ uwh, const half* __restrict__ uwls,
    half* __restrict__ hout, size_t estride, int outw, int routed)
{
    const int e = blockIdx.z;
    const int off = routed ? g_off[e] : 0;
    const int ne  = routed ? (g_off[e+1] - off) : NT;
    const int m0 = blockIdx.x * 128;
    if (m0 >= ne) return;
    const int n0 = blockIdx.y * 64;

    extern __shared__ half smem[];
    int* toks = (int*)(smem + 2*GU_BUFH);

    const int tid = threadIdx.x, wid = tid >> 5, lid = tid & 31;
    const int wr = wid >> 1, wc = wid & 1;
    if (tid < 128) {
        int m = m0 + tid;
        toks[tid] = (m < ne) ? (routed ? g_tok[off + m] : m) : -1;
    }
    __syncthreads();

    const half* gh = gwh + (size_t)e*estride;
    const half* gl = gwls + (size_t)e*estride;
    const half* uh = uwh + (size_t)e*estride;
    const half* ul = uwls + (size_t)e*estride;

    const int ar = tid >> 2, acc_ = tid & 3;
    const int bp = tid >> 6, brow = tid & 63;
    const half* bsrc = (bp == 0 ? gh : bp == 1 ? gl : bp == 2 ? uh : ul)
                       + (size_t)(n0 + brow)*NH;

    auto issue = [&](int c, int buf) {
        const int k0 = c * 32;
        half* bb = smem + buf*GU_BUFH;
        #pragma unroll
        for (int hh = 0; hh < 2; hh++) {
            int row = ar + hh*64;
            int tok = toks[row];
            int sz = (tok >= 0) ? 16 : 0;
            const half* src = g_xh + (size_t)(tok < 0 ? 0 : tok)*NH + k0 + acc_*8;
            cpa16(smem_u32(bb + row*SK + acc_*8), src, sz);
        }
        half* bdst = bb + (128 + bp*64 + brow)*SK;
        #pragma unroll
        for (int cc = 0; cc < 4; cc++)
            cpa16(smem_u32(bdst + cc*8), bsrc + k0 + cc*8, 16);
    };

    float accg[2][4][4] = {}, accu[2][4][4] = {};
    const int NC = NH/32;
    issue(0, 0); CP_COMMIT();
    for (int c = 0; c < NC; ++c) {
        const int buf = c & 1;
        if (c + 1 < NC) { issue(c+1, buf^1); CP_COMMIT(); CP_WAIT1(); }
        else CP_WAIT0();
        __syncthreads();
        const half* bb = smem + buf*GU_BUFH;
        const uint32_t aA = smem_u32(bb);
        const uint32_t aG = smem_u32(bb + 128*SK), aGl = smem_u32(bb + 192*SK);
        const uint32_t aU = smem_u32(bb + 256*SK), aUl = smem_u32(bb + 320*SK);
        #pragma unroll
        for (int ks = 0; ks < 32; ks += 16) {
            uint32_t ah[2][4], as[2][4];
            #pragma unroll
            for (int mi = 0; mi < 2; mi++) {
                uint32_t o = ((wr*32 + mi*16 + (lid & 15))*SK + ks + (lid >> 4)*8)*2;
                ldsm4(ah[mi][0], ah[mi][1], ah[mi][2], ah[mi][3], aA + o);
                #pragma unroll
                for (int j = 0; j < 4; j++) as[mi][j] = hscale(ah[mi][j]);
            }
            #pragma unroll
            for (int nip = 0; nip < 2; nip++) {
                uint32_t o = ((wc*32 + nip*16 + (lid & 7) + (lid >> 4)*8)*SK
                              + ks + ((lid >> 3) & 1)*8)*2;
                uint32_t bg[4], bgl[4], bu[4], bul[4];
                ldsm4(bg[0], bg[1], bg[2], bg[3], aG + o);
                ldsm4(bgl[0], bgl[1], bgl[2], bgl[3], aGl + o);
                ldsm4(bu[0], bu[1], bu[2], bu[3], aU + o);
                ldsm4(bul[0], bul[1], bul[2], bul[3], aUl + o);
                #pragma unroll
                for (int q = 0; q < 2; q++) {
                    const int ni = nip*2 + q;
                    #pragma unroll
                    for (int mi = 0; mi < 2; mi++) {
                        mma16816(accg[mi][ni], ah[mi], bg + q*2);
                        mma16816(accg[mi][ni], as[mi], bgl + q*2);
                        mma16816(accu[mi][ni], ah[mi], bu + q*2);
                        mma16816(accu[mi][ni], as[mi], bul + q*2);
                    }
                }
            }
        }
        __syncthreads();
    }
    #pragma unroll
    for (int mi = 0; mi < 2; mi++) {
        int r0 = wr*32 + mi*16 + (lid >> 2);
        #pragma unroll
        for (int half_ = 0; half_ < 2; half_++) {
            int m = m0 + r0 + half_*8;
            if (m >= ne) continue;
            size_t orow = (size_t)(off + m) * outw;
            #pragma unroll
            for (int ni = 0; ni < 4; ni++) {
                float g0 = accg[mi][ni][half_*2+0], g1 = accg[mi][ni][half_*2+1];
                float u0 = accu[mi][ni][half_*2+0], u1 = accu[mi][ni][half_*2+1];
                float h0 = g0 / (1.f + expf(-g0)) * u0;
                float h1 = g1 / (1.f + expf(-g1)) * u1;
                int nc = n0 + wc*32 + ni*8 + (lid & 3)*2;
                *(__half2*)(hout + orow + nc) = __half2(__float2half(h0), __float2half(h1));
            }
        }
    }
}

// ---------------- down projection MMA (fp16, 2-product) ----------------
#define DN_BUFH (384*SK)
#define DN_SMEM (2*DN_BUFH*2)

__global__ __launch_bounds__(256, 2) void down_mma(
    const half* __restrict__ asrc,
    const half* __restrict__ dwh, const half* __restrict__ dwls,
    float* __restrict__ dst, int Kd, size_t estride, int routed)
{
    const int e = blockIdx.z;
    const int off = routed ? g_off[e] : 0;
    const int ne  = routed ? (g_off[e+1] - off) : NT;
    const int m0 = blockIdx.x * 128;
    if (m0 >= ne) return;
    const int n0 = blockIdx.y * 128;

    extern __shared__ half smem[];
    const int tid = threadIdx.x, wid = tid >> 5, lid = tid & 31;
    const int wr = wid >> 2, wc = wid & 3;

    const half* bh = dwh + (size_t)e*estride;
    const half* bl = dwls + (size_t)e*estride;

    const int ar = tid >> 2, acc_ = tid & 3;
    const int bp = tid >> 7, brow = tid & 127;
    const half* bsrc = (bp == 0 ? bh : bl) + (size_t)(n0 + brow)*Kd;

    auto issue = [&](int c, int buf) {
        const int k0 = c * 32;
        half* bb = smem + buf*DN_BUFH;
        #pragma unroll
        for (int hh = 0; hh < 2; hh++) {
            int row = ar + hh*64;
            int m = m0 + row;
            int sz = (m < ne) ? 16 : 0;
            const half* src = asrc + (size_t)(off + (m < ne ? m : 0))*Kd + k0 + acc_*8;
            cpa16(smem_u32(bb + row*SK + acc_*8), src, sz);
        }
        half* bdst = bb + (128 + bp*128 + brow)*SK;
        #pragma unroll
        for (int cc = 0; cc < 4; cc++)
            cpa16(smem_u32(bdst + cc*8), bsrc + k0 + cc*8, 16);
    };

    float acc[4][4][4] = {};
    const int NC = Kd/32;
    issue(0, 0); CP_COMMIT();
    for (int c = 0; c < NC; ++c) {
        const int buf = c & 1;
        if (c + 1 < NC) { issue(c+1, buf^1); CP_COMMIT(); CP_WAIT1(); }
        else CP_WAIT0();
        __syncthreads();
        const half* bb = smem + buf*DN_BUFH;
        const uint32_t aA = smem_u32(bb);
        const uint32_t aB = smem_u32(bb + 128*SK), aBl = smem_u32(bb + 256*SK);
        #pragma unroll
        for (int ks = 0; ks < 32; ks += 16) {
            uint32_t ah[4][4], as[4][4];
            #pragma unroll
            for (int mi = 0; mi < 4; mi++) {
                uint32_t o = ((wr*64 + mi*16 + (lid & 15))*SK + ks + (lid >> 4)*8)*2;
                ldsm4(ah[mi][0], ah[mi][1], ah[mi][2], ah[mi][3], aA + o);
                #pragma unroll
                for (int j = 0; j < 4; j++) as[mi][j] = hscale(ah[mi][j]);
            }
            #pragma unroll
            for (int nip = 0; nip < 2; nip++) {
                uint32_t o = ((wc*32 + nip*16 + (lid & 7) + (lid >> 4)*8)*SK
                              + ks + ((lid >> 3) & 1)*8)*2;
                uint32_t bbh[4], bbl[4];
                ldsm4(bbh[0], bbh[1], bbh[2], bbh[3], aB + o);
                ldsm4(bbl[0], bbl[1], bbl[2], bbl[3], aBl + o);
                #pragma unroll
                for (int mi = 0; mi < 4; mi++) {
                    #pragma unroll
                    for (int q = 0; q < 2; q++) {
                        const int ni = nip*2 + q;
                        mma16816(acc[mi][ni], ah[mi], bbh + q*2);
                        mma16816(acc[mi][ni], as[mi], bbl + q*2);
                    }
                }
            }
        }
        __syncthreads();
    }
    #pragma unroll
    for (int mi = 0; mi < 4; mi++) {
        int r0 = wr*64 + mi*16 + (lid >> 2);
        #pragma unroll
        for (int half_ = 0; half_ < 2; half_++) {
            int m = m0 + r0 + half_*8;
            if (m >= ne) continue;
            float w = routed ? g_wslot[off + m] : 1.f;
            size_t orow = (size_t)(off + m) * NH;
            #pragma unroll
            for (int ni = 0; ni < 4; ni++) {
                int nc = n0 + wc*32 + ni*8 + (lid & 3)*2;
                float2 o;
                o.x = acc[mi][ni][half_*2+0] * w;
                o.y = acc[mi][ni][half_*2+1] * w;
                *(float2*)(dst + orow + nc) = o;
            }
        }
    }
}

// out[t] += sum_k y[slot[t,k]]
__global__ void combine_kernel(float* __restrict__ out) {
    const int t = blockIdx.x;
    const int c = threadIdx.x;
    const int s0 = g_slot[t*4+0], s1 = g_slot[t*4+1],
              s2 = g_slot[t*4+2], s3 = g_slot[t*4+3];
    const float4* y4 = (const float4*)g_y;
    float4* o4 = (float4*)out;
    float4 o = o4[(size_t)t*256 + c];
    float4 a = y4[(size_t)s0*256 + c];
    float4 b = y4[(size_t)s1*256 + c];
    float4 cc = y4[(size_t)s2*256 + c];
    float4 d = y4[(size_t)s3*256 + c];
    o.x += a.x + b.x + cc.x + d.x;
    o.y += a.y + b.y + cc.y + d.y;
    o.z += a.z + b.z + cc.z + d.z;
    o.w += a.w + b.w + cc.w + d.w;
    o4[(size_t)t*256 + c] = o;
}

extern "C" void kernel_launch(void* const* d_in, const int* in_sizes, int n_in,
                              void* d_out, int out_size) {
    const float* x   = (const float*)d_in[0];
    const float* wr  = (const float*)d_in[1];
    const float* eb  = (const float*)d_in[2];
    const float* gw  = (const float*)d_in[3];
    const float* uw  = (const float*)d_in[4];
    const float* dw  = (const float*)d_in[5];
    const float* sgw = (const float*)d_in[6];
    const float* suw = (const float*)d_in[7];
    const float* sdw = (const float*)d_in[8];
    float* out = (float*)d_out;
    (void)in_sizes; (void)n_in; (void)out_size;

    cudaFuncSetAttribute(gateup_mma, cudaFuncAttributeMaxDynamicSharedMemorySize, GU_SMEM);
    cudaFuncSetAttribute(down_mma,  cudaFuncAttributeMaxDynamicSharedMemorySize, DN_SMEM);

    half *xh, *hh, *shh, *gwh, *gwls, *uwh, *uwls, *dwh, *dwls;
    half *sgwh, *sgwls, *suwh, *suwls, *sdwh, *sdwls;
    cudaGetSymbolAddress((void**)&xh,  g_xh);
    cudaGetSymbolAddress((void**)&hh,  g_hh);
    cudaGetSymbolAddress((void**)&shh, g_shh);
    cudaGetSymbolAddress((void**)&gwh, g_gwh);  cudaGetSymbolAddress((void**)&gwls, g_gwls);
    cudaGetSymbolAddress((void**)&uwh, g_uwh);  cudaGetSymbolAddress((void**)&uwls, g_uwls);
    cudaGetSymbolAddress((void**)&dwh, g_dwh);  cudaGetSymbolAddress((void**)&dwls, g_dwls);
    cudaGetSymbolAddress((void**)&sgwh, g_sgwh); cudaGetSymbolAddress((void**)&sgwls, g_sgwls);
    cudaGetSymbolAddress((void**)&suwh, g_suwh); cudaGetSymbolAddress((void**)&suwls, g_suwls);
    cudaGetSymbolAddress((void**)&sdwh, g_sdwh); cudaGetSymbolAddress((void**)&sdwls, g_sdwls);
    float* yb;
    cudaGetSymbolAddress((void**)&yb, g_y);

    // conversions: 16 elems/thread, 4096 per block (all sizes divide evenly)
    const int NW = NE*NI*NH;            // 8.4M
    const int NS = NISH*NH;             // 1M
    conv_pair_kernel<<<NW/4096, 256>>>(gw,  gwh,  gwls,  NW);
    conv_pair_kernel<<<NW/4096, 256>>>(uw,  uwh,  uwls,  NW);
    conv_pair_kernel<<<NW/4096, 256>>>(dw,  dwh,  dwls,  NW);
    conv_pair_kernel<<<NS/4096, 256>>>(sgw, sgwh, sgwls, NS);
    conv_pair_kernel<<<NS/4096, 256>>>(suw, suwh, suwls, NS);
    conv_pair_kernel<<<NS/4096, 256>>>(sdw, sdwh, sdwls, NS);
    conv_hi_kernel<<<(NT*NH)/4096, 256>>>(x, xh, NT*NH);

    zero_kernel<<<1, 32>>>();
    router_kernel<<<NT, 128>>>(x, wr, eb);
    prefix_kernel<<<1, 1>>>();
    scatter_kernel<<<8, 256>>>();

    // routed gate+up: N = 512, K = 1024
    gateup_mma<<<dim3(64, NI/64, NE), 256, GU_SMEM>>>(
        gwh, gwls, uwh, uwls, hh, (size_t)NI*NH, NI, 1);
    // shared gate+up: N = 1024, K = 1024
    gateup_mma<<<dim3(NT/128, NISH/64, 1), 256, GU_SMEM>>>(
        sgwh, sgwls, suwh, suwls, shh, 0, NISH, 0);
    // routed down: K = 512, N = 1024
    down_mma<<<dim3(64, NH/128, NE), 256, DN_SMEM>>>(
        hh, dwh, dwls, yb, NI, (size_t)NH*NI, 1);
    // shared down: K = 1024, N = 1024 (writes out)
    down_mma<<<dim3(NT/128, NH/128, 1), 256, DN_SMEM>>>(
        shh, sdwh, sdwls, out, NISH, 0, 0);

    combine_kernel<<<NT, 256>>>(out);
}

// round 8
// speedup vs baseline: 1.0076x; 1.0076x over previous
#include <cuda_runtime.h>
#include <cuda_fp16.h>
#include <cstdint>
#include <math.h>

#define NT 2048      // tokens
#define NH 1024      // hidden
#define NE 16        // experts
#define NK 4         // top-k
#define NG 4         // groups
#define NI 512       // moe intermediate
#define NISH 1024    // shared intermediate
#define RSCALE 2.5f
#define NA (NT*NK)
#define SK 40        // smem row stride in halves (32 + 8 pad)
#define INVS (1.f/1024.f)

// ---------------- scratch ----------------
static __device__ int   g_count[NE];
static __device__ int   g_off[NE+1];
static __device__ int   g_cur[NE];
static __device__ int   g_texp[NT*NK];
static __device__ float g_twt[NT*NK];
static __device__ int   g_tok[NA];
static __device__ float g_wslot[NA];
static __device__ int   g_slot[NT*NK];
static __device__ float g_y[(size_t)NA*NH];

// fp16 planes
static __device__ half g_xh [(size_t)NT*NH];
static __device__ half g_hh [(size_t)NA*NI];
static __device__ half g_shh[(size_t)NT*NISH];
static __device__ half g_gwh [(size_t)NE*NI*NH],  g_gwls[(size_t)NE*NI*NH];
static __device__ half g_uwh [(size_t)NE*NI*NH],  g_uwls[(size_t)NE*NI*NH];
static __device__ half g_dwh [(size_t)NE*NH*NI],  g_dwls[(size_t)NE*NH*NI];
static __device__ half g_sgwh[(size_t)NISH*NH],   g_sgwls[(size_t)NISH*NH];
static __device__ half g_suwh[(size_t)NISH*NH],   g_suwls[(size_t)NISH*NH];
static __device__ half g_sdwh[(size_t)NH*NISH],   g_sdwls[(size_t)NH*NISH];

// ---------------- asm helpers ----------------
__device__ __forceinline__ uint32_t smem_u32(const void* p) {
    uint32_t a;
    asm("{ .reg .u64 t; cvta.to.shared.u64 t, %1; cvt.u32.u64 %0, t; }" : "=r"(a) : "l"(p));
    return a;
}
__device__ __forceinline__ void cpa16(uint32_t dst, const void* src, int sz) {
    asm volatile("cp.async.cg.shared.global [%0], [%1], 16, %2;"
        :: "r"(dst), "l"(src), "r"(sz) : "memory");
}
#define CP_COMMIT() asm volatile("cp.async.commit_group;" ::: "memory")
#define CP_WAIT1()  asm volatile("cp.async.wait_group 1;" ::: "memory")
#define CP_WAIT0()  asm volatile("cp.async.wait_group 0;" ::: "memory")

__device__ __forceinline__ void ldsm4(uint32_t& a0, uint32_t& a1, uint32_t& a2, uint32_t& a3,
                                      uint32_t addr) {
    asm volatile("ldmatrix.sync.aligned.m8n8.x4.shared.b16 {%0,%1,%2,%3}, [%4];"
        : "=r"(a0), "=r"(a1), "=r"(a2), "=r"(a3) : "r"(addr));
}
__device__ __forceinline__ void mma16816(float* c, const uint32_t* a, const uint32_t* b) {
    asm volatile("mma.sync.aligned.m16n8k16.row.col.f32.f16.f16.f32 "
        "{%0,%1,%2,%3}, {%4,%5,%6,%7}, {%8,%9}, {%0,%1,%2,%3};"
        : "+f"(c[0]), "+f"(c[1]), "+f"(c[2]), "+f"(c[3])
        : "r"(a[0]), "r"(a[1]), "r"(a[2]), "r"(a[3]), "r"(b[0]), "r"(b[1]));
}
// fp16-accumulate variant for the lo-correction product
__device__ __forceinline__ void mma16816h(uint32_t* c, const uint32_t* a, const uint32_t* b) {
    asm volatile("mma.sync.aligned.m16n8k16.row.col.f16.f16.f16.f16 "
        "{%0,%1}, {%2,%3,%4,%5}, {%6,%7}, {%0,%1};"
        : "+r"(c[0]), "+r"(c[1])
        : "r"(a[0]), "r"(a[1]), "r"(a[2]), "r"(a[3]), "r"(b[0]), "r"(b[1]));
}

// ---------------- fused conversion kernel ----------------
// segments (blocks of 4096 elems): gw 2048 | uw 2048 | dw 2048 | sgw 256 |
// suw 256 | sdw 256 | x 512 (hi only)
__global__ __launch_bounds__(256) void conv_all_kernel(
    const float* __restrict__ gw, const float* __restrict__ uw,
    const float* __restrict__ dw, const float* __restrict__ sgw,
    const float* __restrict__ suw, const float* __restrict__ sdw,
    const float* __restrict__ x)
{
    int b = blockIdx.x;
    const float* src; half* hi; half* lo;
    if      (b < 2048)           { src = gw;  hi = g_gwh;  lo = g_gwls; }
    else if (b < 4096) { b -= 2048; src = uw;  hi = g_uwh;  lo = g_uwls; }
    else if (b < 6144) { b -= 4096; src = dw;  hi = g_dwh;  lo = g_dwls; }
    else if (b < 6400) { b -= 6144; src = sgw; hi = g_sgwh; lo = g_sgwls; }
    else if (b < 6656) { b -= 6400; src = suw; hi = g_suwh; lo = g_suwls; }
    else if (b < 6912) { b -= 6656; src = sdw; hi = g_sdwh; lo = g_sdwls; }
    else               { b -= 6912; src = x;   hi = g_xh;   lo = nullptr; }
    const size_t i = ((size_t)b*256 + threadIdx.x)*16;
    float4 v[4];
    #pragma unroll
    for (int j = 0; j < 4; j++) v[j] = *(const float4*)(src + i + j*4);
    half ho[16], lv[16];
    #pragma unroll
    for (int j = 0; j < 4; j++) {
        const float* f = (const float*)&v[j];
        #pragma unroll
        for (int q = 0; q < 4; q++) {
            half h = __float2half(f[q]);
            ho[j*4+q] = h;
            lv[j*4+q] = __float2half((f[q] - __half2float(h))*1024.f);
        }
    }
    *(uint4*)(hi + i)     = *(uint4*)(ho);
    *(uint4*)(hi + i + 8) = *(uint4*)(ho + 8);
    if (lo) {
        *(uint4*)(lo + i)     = *(uint4*)(lv);
        *(uint4*)(lo + i + 8) = *(uint4*)(lv + 8);
    }
}

// ---------------- routing ----------------
__global__ void zero_kernel() {
    if (threadIdx.x < NE) g_count[threadIdx.x] = 0;
}

__global__ void router_kernel(const float* __restrict__ x,
                              const float* __restrict__ wr,
                              const float* __restrict__ eb) {
    const int t = blockIdx.x;
    __shared__ float xs[NH];
    __shared__ float part[128];
    __shared__ float scores[NE];
    const int tid = threadIdx.x;
    for (int i = tid; i < NH; i += 128) xs[i] = x[(size_t)t*NH + i];
    __syncthreads();
    const int e = tid >> 3, p = tid & 7;
    float s = 0.f;
    const float* w = wr + (size_t)e*NH;
    for (int i = p; i < NH; i += 8) s += xs[i] * w[i];
    part[tid] = s;
    __syncthreads();
    if (tid < NE) {
        float v = 0.f;
        #pragma unroll
        for (int j = 0; j < 8; j++) v += part[tid*8 + j];
        scores[tid] = 1.f / (1.f + expf(-v));
    }
    __syncthreads();
    if (tid == 0) {
        float sc[NE];
        #pragma unroll
        for (int i = 0; i < NE; i++) sc[i] = scores[i] + eb[i];
        float gs[NG];
        #pragma unroll
        for (int g = 0; g < NG; g++) {
            float m1 = -1e30f, m2 = -1e30f;
            #pragma unroll
            for (int j = 0; j < 4; j++) {
                float v = sc[g*4 + j];
                if (v > m1) { m2 = m1; m1 = v; } else if (v > m2) m2 = v;
            }
            gs[g] = m1 + m2;
        }
        int g1 = 0;
        for (int g = 1; g < NG; g++) if (gs[g] > gs[g1]) g1 = g;
        int g2 = -1;
        for (int g = 0; g < NG; g++) {
            if (g == g1) continue;
            if (g2 < 0 || gs[g] > gs[g2]) g2 = g;
        }
        float msk[NE];
        #pragma unroll
        for (int i = 0; i < NE; i++) {
            int gi = i >> 2;
            msk[i] = (gi == g1 || gi == g2) ? sc[i] : 0.0f;
        }
        int idx[NK]; float tw[NK]; float sum = 0.f;
        #pragma unroll
        for (int k = 0; k < NK; k++) {
            int best = 0; float bv = -1e30f;
            for (int i = 0; i < NE; i++)
                if (msk[i] > bv) { bv = msk[i]; best = i; }
            msk[best] = -1e30f;
            idx[k] = best; tw[k] = scores[best]; sum += tw[k];
        }
        const float inv = RSCALE / (sum + 1e-20f);
        for (int k = 0; k < NK; k++) {
            g_texp[t*NK + k] = idx[k];
            g_twt[t*NK + k]  = tw[k] * inv;
            atomicAdd(&g_count[idx[k]], 1);
        }
    }
}

__global__ void prefix_kernel() {
    int o = 0;
    for (int e = 0; e < NE; e++) { g_off[e] = o; g_cur[e] = o; o += g_count[e]; }
    g_off[NE] = o;
}

__global__ void scatter_kernel() {
    int t = blockIdx.x*blockDim.x + threadIdx.x;
    if (t >= NT) return;
    for (int k = 0; k < NK; k++) {
        int e = g_texp[t*NK + k];
        int s = atomicAdd(&g_cur[e], 1);
        g_tok[s] = t;
        g_wslot[s] = g_twt[t*NK + k];
        g_slot[t*NK + k] = s;
    }
}

// ---------------- gate+up fused MMA (routed + shared in one launch) ----------------
#define GU_BUFH (384*SK)
#define GU_SMEM (2*GU_BUFH*2 + 512)

__global__ __launch_bounds__(256, 2) void gateup_mma()
{
    const int z = blockIdx.z;
    const int routed = (z < NE);
    if (routed && blockIdx.y >= NI/64) return;
    const int e = routed ? z : 0;
    const int off = routed ? g_off[e] : 0;
    const int ne  = routed ? (g_off[e+1] - off) : NT;
    const int m0 = blockIdx.x * 128;
    if (m0 >= ne) return;
    const int n0 = blockIdx.y * 64;
    const int outw = routed ? NI : NISH;
    half* hout = routed ? g_hh : g_shh;

    const size_t wb = routed ? (size_t)e*NI*NH : 0;
    const half* gh = (routed ? g_gwh  : g_sgwh)  + wb;
    const half* gl = (routed ? g_gwls : g_sgwls) + wb;
    const half* uh = (routed ? g_uwh  : g_suwh)  + wb;
    const half* ul = (routed ? g_uwls : g_suwls) + wb;

    extern __shared__ half smem[];
    int* toks = (int*)(smem + 2*GU_BUFH);

    const int tid = threadIdx.x, wid = tid >> 5, lid = tid & 31;
    const int wr = wid >> 1, wc = wid & 1;
    if (tid < 128) {
        int m = m0 + tid;
        toks[tid] = (m < ne) ? (routed ? g_tok[off + m] : m) : -1;
    }
    __syncthreads();

    const int ar = tid >> 2, acc_ = tid & 3;
    const int bp = tid >> 6, brow = tid & 63;
    const half* bsrc = (bp == 0 ? gh : bp == 1 ? gl : bp == 2 ? uh : ul)
                       + (size_t)(n0 + brow)*NH;

    auto issue = [&](int c, int buf) {
        const int k0 = c * 32;
        half* bb = smem + buf*GU_BUFH;
        #pragma unroll
        for (int hh2 = 0; hh2 < 2; hh2++) {
            int row = ar + hh2*64;
            int tok = toks[row];
            int sz = (tok >= 0) ? 16 : 0;
            const half* src = g_xh + (size_t)(tok < 0 ? 0 : tok)*NH + k0 + acc_*8;
            cpa16(smem_u32(bb + row*SK + acc_*8), src, sz);
        }
        half* bdst = bb + (128 + bp*64 + brow)*SK;
        #pragma unroll
        for (int cc = 0; cc < 4; cc++)
            cpa16(smem_u32(bdst + cc*8), bsrc + k0 + cc*8, 16);
    };

    float accg[2][4][4] = {}, accu[2][4][4] = {};
    uint32_t acchg[2][4][2] = {}, acchu[2][4][2] = {};
    const int NC = NH/32;
    issue(0, 0); CP_COMMIT();
    for (int c = 0; c < NC; ++c) {
        const int buf = c & 1;
        if (c + 1 < NC) { issue(c+1, buf^1); CP_COMMIT(); CP_WAIT1(); }
        else CP_WAIT0();
        __syncthreads();
        const half* bb = smem + buf*GU_BUFH;
        const uint32_t aA = smem_u32(bb);
        const uint32_t aG = smem_u32(bb + 128*SK), aGl = smem_u32(bb + 192*SK);
        const uint32_t aU = smem_u32(bb + 256*SK), aUl = smem_u32(bb + 320*SK);
        #pragma unroll
        for (int ks = 0; ks < 32; ks += 16) {
            uint32_t ah[2][4];
            #pragma unroll
            for (int mi = 0; mi < 2; mi++) {
                uint32_t o = ((wr*32 + mi*16 + (lid & 15))*SK + ks + (lid >> 4)*8)*2;
                ldsm4(ah[mi][0], ah[mi][1], ah[mi][2], ah[mi][3], aA + o);
            }
            #pragma unroll
            for (int nip = 0; nip < 2; nip++) {
                uint32_t o = ((wc*32 + nip*16 + (lid & 7) + (lid >> 4)*8)*SK
                              + ks + ((lid >> 3) & 1)*8)*2;
                uint32_t bg[4], bgl[4], bu[4], bul[4];
                ldsm4(bg[0], bg[1], bg[2], bg[3], aG + o);
                ldsm4(bgl[0], bgl[1], bgl[2], bgl[3], aGl + o);
                ldsm4(bu[0], bu[1], bu[2], bu[3], aU + o);
                ldsm4(bul[0], bul[1], bul[2], bul[3], aUl + o);
                #pragma unroll
                for (int q = 0; q < 2; q++) {
                    const int ni = nip*2 + q;
                    #pragma unroll
                    for (int mi = 0; mi < 2; mi++) {
                        mma16816(accg[mi][ni], ah[mi], bg + q*2);
                        mma16816h(acchg[mi][ni], ah[mi], bgl + q*2);
                        mma16816(accu[mi][ni], ah[mi], bu + q*2);
                        mma16816h(acchu[mi][ni], ah[mi], bul + q*2);
                    }
                }
            }
        }
        __syncthreads();
    }
    #pragma unroll
    for (int mi = 0; mi < 2; mi++) {
        int r0 = wr*32 + mi*16 + (lid >> 2);
        #pragma unroll
        for (int half_ = 0; half_ < 2; half_++) {
            int m = m0 + r0 + half_*8;
            if (m >= ne) continue;
            size_t orow = (size_t)(off + m) * outw;
            #pragma unroll
            for (int ni = 0; ni < 4; ni++) {
                __half2 lg = *((__half2*)&acchg[mi][ni][half_]);
                __half2 lu = *((__half2*)&acchu[mi][ni][half_]);
                float g0 = accg[mi][ni][half_*2+0] + __low2float(lg)*INVS;
                float g1 = accg[mi][ni][half_*2+1] + __high2float(lg)*INVS;
                float u0 = accu[mi][ni][half_*2+0] + __low2float(lu)*INVS;
                float u1 = accu[mi][ni][half_*2+1] + __high2float(lu)*INVS;
                float h0 = g0 / (1.f + expf(-g0)) * u0;
                float h1 = g1 / (1.f + expf(-g1)) * u1;
                int nc = n0 + wc*32 + ni*8 + (lid & 3)*2;
                *(__half2*)(hout + orow + nc) = __half2(__float2half(h0), __float2half(h1));
            }
        }
    }
}

// ---------------- down projection MMA (routed + shared in one launch) ----------------
#define DN_BUFH (384*SK)
#define DN_SMEM (2*DN_BUFH*2)

__global__ __launch_bounds__(256, 2) void down_mma(float* __restrict__ outp)
{
    const int z = blockIdx.z;
    const int routed = (z < NE);
    const int e = routed ? z : 0;
    const int off = routed ? g_off[e] : 0;
    const int ne  = routed ? (g_off[e+1] - off) : NT;
    const int m0 = blockIdx.x * 128;
    if (m0 >= ne) return;
    const int n0 = blockIdx.y * 128;
    const int Kd = routed ? NI : NISH;
    const half* asrc = routed ? g_hh : g_shh;
    float* dst = routed ? g_y : outp;

    const size_t wb = routed ? (size_t)e*NH*NI : 0;
    const half* bh = (routed ? g_dwh  : g_sdwh)  + wb;
    const half* bl = (routed ? g_dwls : g_sdwls) + wb;

    extern __shared__ half smem[];
    const int tid = threadIdx.x, wid = tid >> 5, lid = tid & 31;
    const int wr = wid >> 2, wc = wid & 3;

    const int ar = tid >> 2, acc_ = tid & 3;
    const int bp = tid >> 7, brow = tid & 127;
    const half* bsrc = (bp == 0 ? bh : bl) + (size_t)(n0 + brow)*Kd;

    auto issue = [&](int c, int buf) {
        const int k0 = c * 32;
        half* bb = smem + buf*DN_BUFH;
        #pragma unroll
        for (int hh2 = 0; hh2 < 2; hh2++) {
            int row = ar + hh2*64;
            int m = m0 + row;
            int sz = (m < ne) ? 16 : 0;
            const half* src = asrc + (size_t)(off + (m < ne ? m : 0))*Kd + k0 + acc_*8;
            cpa16(smem_u32(bb + row*SK + acc_*8), src, sz);
        }
        half* bdst = bb + (128 + bp*128 + brow)*SK;
        #pragma unroll
        for (int cc = 0; cc < 4; cc++)
            cpa16(smem_u32(bdst + cc*8), bsrc + k0 + cc*8, 16);
    };

    float acc[4][4][4] = {};
    uint32_t acch[4][4][2] = {};
    const int NC = Kd/32;
    issue(0, 0); CP_COMMIT();
    for (int c = 0; c < NC; ++c) {
        const int buf = c & 1;
        if (c + 1 < NC) { issue(c+1, buf^1); CP_COMMIT(); CP_WAIT1(); }
        else CP_WAIT0();
        __syncthreads();
        const half* bb = smem + buf*DN_BUFH;
        const uint32_t aA = smem_u32(bb);
        const uint32_t aB = smem_u32(bb + 128*SK), aBl = smem_u32(bb + 256*SK);
        #pragma unroll
        for (int ks = 0; ks < 32; ks += 16) {
            uint32_t ah[4][4];
            #pragma unroll
            for (int mi = 0; mi < 4; mi++) {
                uint32_t o = ((wr*64 + mi*16 + (lid & 15))*SK + ks + (lid >> 4)*8)*2;
                ldsm4(ah[mi][0], ah[mi][1], ah[mi][2], ah[mi][3], aA + o);
            }
            #pragma unroll
            for (int nip = 0; nip < 2; nip++) {
                uint32_t o = ((wc*32 + nip*16 + (lid & 7) + (lid >> 4)*8)*SK
                              + ks + ((lid >> 3) & 1)*8)*2;
                uint32_t bbh[4], bbl[4];
                ldsm4(bbh[0], bbh[1], bbh[2], bbh[3], aB + o);
                ldsm4(bbl[0], bbl[1], bbl[2], bbl[3], aBl + o);
                #pragma unroll
                for (int mi = 0; mi < 4; mi++) {
                    #pragma unroll
                    for (int q = 0; q < 2; q++) {
                        const int ni = nip*2 + q;
                        mma16816(acc[mi][ni], ah[mi], bbh + q*2);
                        mma16816h(acch[mi][ni], ah[mi], bbl + q*2);
                    }
                }
            }
        }
        __syncthreads();
    }
    #pragma unroll
    for (int mi = 0; mi < 4; mi++) {
        int r0 = wr*64 + mi*16 + (lid >> 2);
        #pragma unroll
        for (int half_ = 0; half_ < 2; half_++) {
            int m = m0 + r0 + half_*8;
            if (m >= ne) continue;
            float w = routed ? g_wslot[off + m] : 1.f;
            size_t orow = (size_t)(off + m) * NH;
            #pragma unroll
            for (int ni = 0; ni < 4; ni++) {
                __half2 lp = *((__half2*)&acch[mi][ni][half_]);
                int nc = n0 + wc*32 + ni*8 + (lid & 3)*2;
                float2 o;
                o.x = (acc[mi][ni][half_*2+0] + __low2float(lp)*INVS) * w;
                o.y = (acc[mi][ni][half_*2+1] + __high2float(lp)*INVS) * w;
                *(float2*)(dst + orow + nc) = o;
            }
        }
    }
}

// out[t] += sum_k y[slot[t,k]]
__global__ void combine_kernel(float* __restrict__ out) {
    const int t = blockIdx.x;
    const int c = threadIdx.x;
    const int s0 = g_slot[t*4+0], s1 = g_slot[t*4+1],
              s2 = g_slot[t*4+2], s3 = g_slot[t*4+3];
    const float4* y4 = (const float4*)g_y;
    float4* o4 = (float4*)out;
    float4 o = o4[(size_t)t*256 + c];
    float4 a = y4[(size_t)s0*256 + c];
    float4 b = y4[(size_t)s1*256 + c];
    float4 cc = y4[(size_t)s2*256 + c];
    float4 d = y4[(size_t)s3*256 + c];
    o.x += a.x + b.x + cc.x + d.x;
    o.y += a.y + b.y + cc.y + d.y;
    o.z += a.z + b.z + cc.z + d.z;
    o.w += a.w + b.w + cc.w + d.w;
    o4[(size_t)t*256 + c] = o;
}

extern "C" void kernel_launch(void* const* d_in, const int* in_sizes, int n_in,
                              void* d_out, int out_size) {
    const float* x   = (const float*)d_in[0];
    const float* wr  = (const float*)d_in[1];
    const float* eb  = (const float*)d_in[2];
    const float* gw  = (const float*)d_in[3];
    const float* uw  = (const float*)d_in[4];
    const float* dw  = (const float*)d_in[5];
    const float* sgw = (const float*)d_in[6];
    const float* suw = (const float*)d_in[7];
    const float* sdw = (const float*)d_in[8];
    float* out = (float*)d_out;
    (void)in_sizes; (void)n_in; (void)out_size;

    cudaFuncSetAttribute(gateup_mma, cudaFuncAttributeMaxDynamicSharedMemorySize, GU_SMEM);
    cudaFuncSetAttribute(down_mma,  cudaFuncAttributeMaxDynamicSharedMemorySize, DN_SMEM);

    conv_all_kernel<<<7424, 256>>>(gw, uw, dw, sgw, suw, sdw, x);

    zero_kernel<<<1, 32>>>();
    router_kernel<<<NT, 128>>>(x, wr, eb);
    prefix_kernel<<<1, 1>>>();
    scatter_kernel<<<8, 256>>>();

    // fused gate+up: z<16 routed (y<8 active), z=16 shared
    gateup_mma<<<dim3(16, 16, NE+1), 256, GU_SMEM>>>();
    // fused down: z<16 routed (K=512), z=16 shared (K=1024, writes out)
    down_mma<<<dim3(16, 8, NE+1), 256, DN_SMEM>>>(out);

    combine_kernel<<<NT, 256>>>(out);
}